// round 14
// baseline (speedup 1.0000x reference)
#include <cuda_runtime.h>
#include <cuda_fp16.h>
#include <stdint.h>

#define NN 100000
#define NE 800000
#define C  100
#define OC 50
#define NBLK ((NN + 1023) / 1024)

#define TM 128
#define NTILES ((NN + TM - 1) / TM)
#define GEMM_GRID 296            // 2 CTAs per SM
#define GEMM_THREADS 256

// word stride per row: reads touch words 0..55; WS=60 -> conflict-free frags
#define WS 60
#define SA0 0
#define SA1 (TM * WS)                  // 7680
#define SB  (2 * TM * WS)              // 15360
#define SM_WORDS (SB + 104 * WS)       // 21600 words = 86400 B (2 CTAs/SM)

#define CVT_QUADS (NN * 25)

// ---------------- device globals (scratch; zero-init at load) ----------------
__device__ __align__(16) float d_dis[NN];
__device__ __align__(16) __half d_X16[NN * C];   // x pre-converted to fp16
__device__ __align__(16) __half d_G16[NN * C];
__device__ __align__(16) __half d_H16[NN * C];
__device__ int d_cnt[NN];      // re-zeroed at tail of gather mode 1 each run
__device__ int d_start[NN];    // after fused fill: END pointers
__device__ int d_csr[NE];
__device__ int d_total;        // re-zeroed at tail of gather mode 1 each run

// ---------------- PTX helpers (baseline, sm_80+) ----------------
__device__ __forceinline__ void mma_f16(float* d, const uint32_t* a, const uint32_t* b) {
    asm volatile(
        "mma.sync.aligned.m16n8k16.row.col.f32.f16.f16.f32 "
        "{%0,%1,%2,%3}, {%4,%5,%6,%7}, {%8,%9}, {%0,%1,%2,%3};"
        : "+f"(d[0]), "+f"(d[1]), "+f"(d[2]), "+f"(d[3])
        : "r"(a[0]), "r"(a[1]), "r"(a[2]), "r"(a[3]), "r"(b[0]), "r"(b[1]));
}
__device__ __forceinline__ void cp_async8(uint32_t saddr, const void* g, int src_sz) {
    asm volatile("cp.async.ca.shared.global [%0], [%1], 8, %2;"
                 :: "r"(saddr), "l"(g), "r"(src_sz));
}
#define CP_COMMIT() asm volatile("cp.async.commit_group;" ::: "memory")
#define CP_WAIT1()  asm volatile("cp.async.wait_group 1;" ::: "memory")

// ---------------- CSR build pieces ----------------
__global__ void k_degcvt(const int* __restrict__ dst, const float* __restrict__ x) {
    int i = blockIdx.x * blockDim.x + threadIdx.x;
    if (i < NE) atomicAdd(&d_cnt[dst[i]], 1);    // cnt pre-zeroed
    if (i < CVT_QUADS) {
        int r = i / 25, c4 = (i % 25) * 4;
        float4 v = *(const float4*)&x[(size_t)r * C + c4];
        __half2 h0 = __floats2half2_rn(v.x, v.y);
        __half2 h1 = __floats2half2_rn(v.z, v.w);
        uint2 w2;
        w2.x = *reinterpret_cast<uint32_t*>(&h0);
        w2.y = *reinterpret_cast<uint32_t*>(&h1);
        *(uint2*)&d_X16[(size_t)r * C + c4] = w2;
    }
}

// block scan + single global atomic base alloc; also dis = rsqrt(cnt+1)
__global__ void k_alloc() {
    __shared__ int sh[1024];
    __shared__ int sbase;
    int i = blockIdx.x * 1024 + threadIdx.x;
    int v = (i < NN) ? d_cnt[i] : 0;
    sh[threadIdx.x] = v;
    __syncthreads();
    for (int off = 1; off < 1024; off <<= 1) {
        int t = (threadIdx.x >= off) ? sh[threadIdx.x - off] : 0;
        __syncthreads();
        sh[threadIdx.x] += t;
        __syncthreads();
    }
    if (threadIdx.x == 1023) sbase = atomicAdd(&d_total, sh[1023]);
    __syncthreads();
    if (i < NN) {
        d_start[i] = sbase + sh[threadIdx.x] - v;   // exclusive start
        d_dis[i] = rsqrtf((float)v + 1.0f);
    }
}

// ---------------- fp16 GEMM, cp.async double-buffered; mode 0 also fills CSR ----
// G16 = dis[row] * (A @ W); A always fp16 (d_X16 or d_H16)
// mode 0: W = W0 [C x C], fused CSR fill (d_start/d_dis ready from k_alloc)
// mode 1: W = [Wa | Wb] column-concat
__device__ __forceinline__ void issue_tile(int t, const __half* __restrict__ A,
                                           uint32_t sa_u32, int tid) {
    const int i0 = t * TM;
    const int rowlim = NN - i0;
    #pragma unroll
    for (int it = 0; it < 13; it++) {
        int q = it * 256 + tid;
        if (q < TM * 25) {
            int r = q / 25, c4 = (q % 25) * 4;
            int ok = (r < rowlim);
            const __half* src = &A[(size_t)(i0 + (ok ? r : 0)) * C + c4];
            cp_async8(sa_u32 + (uint32_t)(r * WS + (c4 >> 1)) * 4, src, ok ? 8 : 0);
        }
    }
}

__global__ void __launch_bounds__(GEMM_THREADS, 2)
k_gemm(const __half* __restrict__ A, const float* __restrict__ W0,
       const float* __restrict__ Wa, const float* __restrict__ Wb,
       int mode, const int* __restrict__ esrc, const int* __restrict__ edst) {
    extern __shared__ uint32_t sm[];
    const int tid = threadIdx.x, wid = tid >> 5, lane = tid & 31;
    const int g = lane >> 2, tg = lane & 3;
    const uint32_t smb = (uint32_t)__cvta_generic_to_shared(sm);

    // fused CSR fill (mode 0): cursor atomics + csr stores drain during MMA work
    if (mode == 0) {
        for (int e = blockIdx.x * GEMM_THREADS + tid; e < NE;
             e += GEMM_GRID * GEMM_THREADS) {
            int d = edst[e];
            int p = atomicAdd(&d_start[d], 1);   // start[] becomes END pointers
            d_csr[p] = esrc[e];
        }
    }

    for (int i = tid; i < SM_WORDS; i += GEMM_THREADS) sm[i] = 0;
    __syncthreads();   // zero done before any cp.async writes

    // stage W -> fp16; layout B[n][kword]
    for (int idx = tid; idx < C * C; idx += GEMM_THREADS) {
        int k = idx / C, n = idx % C;
        float w = (mode == 0) ? W0[idx]
                              : ((n < OC) ? Wa[k * OC + n] : Wb[k * OC + (n - OC)]);
        ((__half*)(sm + SB))[(n * WS + (k >> 1)) * 2 + (k & 1)] = __float2half_rn(w);
    }

    const int r0 = wid * 16;   // 8 warps x 16 rows = 128
    const int stride = GEMM_GRID;
    int t = blockIdx.x;
    int buf = 0;               // buffer holding tile t
    if (t < NTILES) issue_tile(t, A, smb + SA0 * 4, tid);
    CP_COMMIT();

    for (; t < NTILES; t += stride) {
        int tn = t + stride;
        if (tn < NTILES)
            issue_tile(tn, A, smb + (buf ? SA0 : SA1) * 4, tid);
        CP_COMMIT();
        CP_WAIT1();            // oldest group (tile t) complete
        __syncthreads();       // also covers W staging on first iteration

        const uint32_t* sa = sm + (buf ? SA1 : SA0);

        float acc[13][4];
        #pragma unroll
        for (int nt = 0; nt < 13; nt++)
            #pragma unroll
            for (int q = 0; q < 4; q++) acc[nt][q] = 0.f;

        #pragma unroll
        for (int kt = 0; kt < 7; kt++) {
            const int kw = kt * 8;
            uint32_t a[4];
            a[0] = sa[(r0 + g) * WS + kw + tg];
            a[1] = sa[(r0 + g + 8) * WS + kw + tg];
            a[2] = sa[(r0 + g) * WS + kw + 4 + tg];
            a[3] = sa[(r0 + g + 8) * WS + kw + 4 + tg];
            #pragma unroll
            for (int nt = 0; nt < 13; nt++) {
                const int n0 = nt * 8;
                uint32_t b[2];
                b[0] = sm[SB + (n0 + g) * WS + kw + tg];
                b[1] = sm[SB + (n0 + g) * WS + kw + 4 + tg];
                mma_f16(acc[nt], a, b);
            }
        }

        const int i0 = t * TM;
        const int row1 = i0 + r0 + g, row2 = row1 + 8;
        const float s1 = (row1 < NN) ? d_dis[row1] : 0.f;
        const float s2 = (row2 < NN) ? d_dis[row2] : 0.f;
        #pragma unroll
        for (int nt = 0; nt < 13; nt++) {
            const int c = nt * 8 + 2 * tg;
            if (c < C) {
                if (row1 < NN)
                    *(__half2*)&d_G16[(size_t)row1 * C + c] =
                        __floats2half2_rn(s1 * acc[nt][0], s1 * acc[nt][1]);
                if (row2 < NN)
                    *(__half2*)&d_G16[(size_t)row2 * C + c] =
                        __floats2half2_rn(s2 * acc[nt][2], s2 * acc[nt][3]);
            }
        }
        __syncthreads();   // smem reads done before this buffer is refilled
        buf ^= 1;
    }
}

// ---------------- gather + epilogues ----------------
__device__ __forceinline__ float4 ldg_h4(const __half* p) {
    uint2 r = *(const uint2*)p;
    __half2 a = *reinterpret_cast<__half2*>(&r.x);
    __half2 b = *reinterpret_cast<__half2*>(&r.y);
    float2 f0 = __half22float2(a), f1 = __half22float2(b);
    return make_float4(f0.x, f0.y, f1.x, f1.y);
}

__global__ void k_gather(int mode, const float* __restrict__ b1,
                         const float* __restrict__ bmu, const float* __restrict__ bls,
                         float* __restrict__ out) {
    int w = (blockIdx.x * blockDim.x + threadIdx.x) >> 5;
    int lane = threadIdx.x & 31;
    if (mode == 1 && blockIdx.x == 0 && threadIdx.x == 0) d_total = 0;  // reset
    if (w >= NN || lane >= 25) return;
    int en = d_start[w];           // END pointer (post-fill)
    int n  = d_cnt[w];
    if (mode == 1 && lane == 0) d_cnt[w] = 0;   // reset for next run (post-read)
    int st = en - n;
    int p4 = lane * 4;

    float4 acc = ldg_h4(&d_G16[(size_t)w * C + p4]);   // self-loop term
    for (int j = 0; j < n; j++) {
        int s = d_csr[st + j];
        float4 v = ldg_h4(&d_G16[(size_t)s * C + p4]);
        acc.x += v.x; acc.y += v.y; acc.z += v.z; acc.w += v.w;
    }
    float sc = d_dis[w];

    if (mode == 0) {
        float4 bb = *(const float4*)&b1[p4];
        __half2 h0 = __floats2half2_rn(fmaxf(fmaf(sc, acc.x, bb.x), 0.f),
                                       fmaxf(fmaf(sc, acc.y, bb.y), 0.f));
        __half2 h1 = __floats2half2_rn(fmaxf(fmaf(sc, acc.z, bb.z), 0.f),
                                       fmaxf(fmaf(sc, acc.w, bb.w), 0.f));
        uint2 packed;
        packed.x = *reinterpret_cast<uint32_t*>(&h0);
        packed.y = *reinterpret_cast<uint32_t*>(&h1);
        *(uint2*)&d_H16[(size_t)w * C + p4] = packed;
    } else {
        float v[4] = { sc * acc.x, sc * acc.y, sc * acc.z, sc * acc.w };
        #pragma unroll
        for (int q = 0; q < 4; q++) {
            int c = p4 + q;
            if (c < OC) out[(size_t)w * OC + c]                          = v[q] + bmu[c];
            else        out[(size_t)NN * OC + (size_t)w * OC + (c - OC)] = v[q] + bls[c - OC];
        }
    }
}

extern "C" void kernel_launch(void* const* d_in, const int* in_sizes, int n_in,
                              void* d_out, int out_size) {
    const float* x   = (const float*)d_in[0];
    const int*   ei  = (const int*)  d_in[1];
    const float* W1  = (const float*)d_in[2];
    const float* b1  = (const float*)d_in[3];
    const float* Wmu = (const float*)d_in[4];
    const float* bmu = (const float*)d_in[5];
    const float* Wls = (const float*)d_in[6];
    const float* bls = (const float*)d_in[7];
    float* out = (float*)d_out;

    const int* src = ei;
    const int* dst = ei + NE;

    __half* x16_ptr;  cudaGetSymbolAddress((void**)&x16_ptr, d_X16);
    __half* h16_ptr;  cudaGetSymbolAddress((void**)&h16_ptr, d_H16);

    cudaFuncSetAttribute(k_gemm, cudaFuncAttributeMaxDynamicSharedMemorySize, SM_WORDS * 4);

    // CSR counts + x->fp16 (fused), then range alloc (also computes d_dis)
    k_degcvt<<<(CVT_QUADS + 255) / 256, 256>>>(dst, x);
    k_alloc<<<NBLK, 1024>>>();

    // layer 1 GEMM with fused CSR fill (fill drains during MMA work)
    k_gemm<<<GEMM_GRID, GEMM_THREADS, SM_WORDS * 4>>>(x16_ptr, W1, nullptr, nullptr, 0, src, dst);
    k_gather<<<(NN * 32 + 255) / 256, 256>>>(0, b1, nullptr, nullptr, nullptr);

    // layers 2+3 fused (mu | logstd column-concat)
    k_gemm<<<GEMM_GRID, GEMM_THREADS, SM_WORDS * 4>>>(h16_ptr, nullptr, Wmu, Wls, 1, nullptr, nullptr);
    k_gather<<<(NN * 32 + 255) / 256, 256>>>(1, nullptr, bmu, bls, out);
}